// round 8
// baseline (speedup 1.0000x reference)
#include <cuda_runtime.h>

#define M 8192
#define NT 25          // Taylor terms n = 0..24

// Scratch (allocation-free rule: __device__ globals). No counters, no
// accumulator globals -> every launch is stateless & graph-replayable.
__device__ float g_q[M], g_k[M], g_v[M];

// ---------------------------------------------------------------------------
// K1: fused triple GEMV  y = W @ x + b  (classic grid; best measured config:
// ~120us @ ~83% DRAM with __ldcs streaming weight loads).
// ---------------------------------------------------------------------------
__global__ void __launch_bounds__(256) gemv3_kernel(
    const float* __restrict__ x,
    const float* __restrict__ Wq, const float* __restrict__ bq,
    const float* __restrict__ Wk, const float* __restrict__ bk,
    const float* __restrict__ Wv, const float* __restrict__ bv)
{
    __shared__ float4 sx[M / 4];          // 32 KB
    const int tid = threadIdx.x;

    const float4* x4 = reinterpret_cast<const float4*>(x);
#pragma unroll
    for (int i = 0; i < (M / 4) / 256; i++)
        sx[tid + i * 256] = x4[tid + i * 256];
    __syncthreads();

    const int mat  = blockIdx.x >> 10;    // 0:q 1:k 2:v
    const int blk  = blockIdx.x & 1023;
    const int warp = tid >> 5;
    const int lane = tid & 31;
    const int row  = blk * 8 + warp;

    const float* W;
    const float* b;
    float*       y;
    if (mat == 0)      { W = Wq; b = bq; y = g_q; }
    else if (mat == 1) { W = Wk; b = bk; y = g_k; }
    else               { W = Wv; b = bv; y = g_v; }

    const float4* Wr = reinterpret_cast<const float4*>(W + (size_t)row * M);

    float sum = 0.f;
#pragma unroll 8
    for (int c = lane; c < M / 4; c += 32) {
        float4 w  = __ldcs(&Wr[c]);       // streaming: read-once, evict-first
        float4 xx = sx[c];
        sum += w.x * xx.x + w.y * xx.y + w.z * xx.z + w.w * xx.w;
    }
#pragma unroll
    for (int o = 16; o; o >>= 1)
        sum += __shfl_xor_sync(0xffffffffu, sum, o);
    if (lane == 0)
        y[row] = sum + b[row];
}

// ---------------------------------------------------------------------------
// K2: moments + finalize, SINGLE block of 512 threads — no grid barrier, no
// global atomics, no device state.
//   Phase A: C_n = sum_j k_j^n/n!, D_n = sum_j k_j^n v_j/n!  (16 j per thread,
//            register accumulators -> warp shuffle -> shared atomics)
//   Phase B: __syncthreads (block-internal, ~7 cyc)
//   Phase C: out[i] = Horner(D)(a_i) / Horner(C)(a_i),  a_i = q_i/32
//            (16 rows per thread, coefficients staged into registers)
// ---------------------------------------------------------------------------
__global__ void __launch_bounds__(512) tail_kernel(float* __restrict__ out)
{
    __shared__ float sC[NT], sD[NT];
    const int tid = threadIdx.x;
    if (tid < NT) { sC[tid] = 0.f; sD[tid] = 0.f; }
    __syncthreads();

    // ---- Phase A: moment accumulation ----
    float C[NT], D[NT];
#pragma unroll
    for (int n = 0; n < NT; n++) { C[n] = 0.f; D[n] = 0.f; }

#pragma unroll
    for (int i = 0; i < M / 512; i++) {
        const int j = i * 512 + tid;
        const float k = g_k[j];
        const float v = g_v[j];
        float term = 1.f;                 // k^n / n!
#pragma unroll
        for (int n = 0; n < NT; n++) {
            C[n] += term;
            D[n] += term * v;
            term *= k * (1.0f / (float)(n + 1));
        }
    }

#pragma unroll
    for (int n = 0; n < NT; n++) {
#pragma unroll
        for (int o = 16; o; o >>= 1) {
            C[n] += __shfl_xor_sync(0xffffffffu, C[n], o);
            D[n] += __shfl_xor_sync(0xffffffffu, D[n], o);
        }
    }
    if ((tid & 31) == 0) {
#pragma unroll
        for (int n = 0; n < NT; n++) {
            atomicAdd(&sC[n], C[n]);      // 16-way, 50 spread banks
            atomicAdd(&sD[n], D[n]);
        }
    }
    __syncthreads();                      // ---- Phase B ----

    // ---- Phase C: Horner finalize, coefficients in registers ----
#pragma unroll
    for (int n = 0; n < NT; n++) { C[n] = sC[n]; D[n] = sD[n]; }

#pragma unroll
    for (int i = 0; i < M / 512; i++) {
        const int r = i * 512 + tid;
        const float a = g_q[r] * 0.03125f;    // 1/sqrt(1024) = 1/32
        float s0 = C[NT - 1];
        float s1 = D[NT - 1];
#pragma unroll
        for (int n = NT - 2; n >= 0; n--) {
            s0 = fmaf(s0, a, C[n]);
            s1 = fmaf(s1, a, D[n]);
        }
        out[r] = s1 / s0;
    }
}

// ---------------------------------------------------------------------------
extern "C" void kernel_launch(void* const* d_in, const int* in_sizes, int n_in,
                              void* d_out, int out_size)
{
    const float* x  = (const float*)d_in[0];
    const float* Wq = (const float*)d_in[1];
    const float* bq = (const float*)d_in[2];
    const float* Wk = (const float*)d_in[3];
    const float* bk = (const float*)d_in[4];
    const float* Wv = (const float*)d_in[5];
    const float* bv = (const float*)d_in[6];

    gemv3_kernel<<<3072, 256>>>(x, Wq, bq, Wk, bk, Wv, bv);
    tail_kernel<<<1, 512>>>((float*)d_out);
}